// round 7
// baseline (speedup 1.0000x reference)
#include <cuda_runtime.h>
#include <cstdint>
#include <math.h>

#define NTOK 8192
#define CDIM 64
#define NEXP 16
#define CAP  640
#define NEC  ((size_t)NTOK * NEXP * CAP)       /* 83,886,080 elements */
#define SCALAR_OFF (2 * NEC)                   /* z, aux, std */
#define LOGITS_OFF (2 * NEC + 3)

// ---------------- scratch (no allocs allowed) ----------------
__device__ float              g_probs[NTOK * NEXP];
__device__ float              g_lse2[NTOK];
__device__ unsigned long long g_keys[NTOK];
__device__ int                g_expert[NTOK];
__device__ int                g_bcnt[NEXP];
__device__ unsigned long long g_bkeys[NEXP * NTOK];   // per-expert key buckets (1MB)

// ---------------- kernel 0: zero bucket counters ----------------
__global__ void init_kernel() {
    if (threadIdx.x < NEXP) g_bcnt[threadIdx.x] = 0;
}

// ---------------- kernel 1: pool + gate + softmax + bucket scatter ----------
// warp-per-token, 8 tokens per 256-thread block, no block-wide barriers
__global__ void __launch_bounds__(256) gating_kernel(const float* __restrict__ X,
                              const float* __restrict__ Wg,
                              const float* __restrict__ bg,
                              float* __restrict__ out_logits) {
    __shared__ float pooled_s[8][CDIM];
    const int warp = threadIdx.x >> 5;
    const int l    = threadIdx.x & 31;
    const int n    = blockIdx.x * 8 + warp;
    float* pooled = pooled_s[warp];

    // 32 coalesced LDG.128 per lane (front-batched, high MLP).
    // f4 index = k*32 + l; channel = idx>>4 = 2k + (l>>4).
    const float4* xp = (const float4*)(X + (size_t)n * (CDIM * 64));
    float s[32];
#pragma unroll
    for (int k = 0; k < 32; k++) {
        float4 v = xp[k * 32 + l];
        s[k] = (v.x + v.y) + (v.z + v.w);
    }
    // 32 independent half-warp (16-lane) reductions; offsets 8,4,2,1 keep
    // the two 16-lane groups separate (bit4 preserved).
#pragma unroll
    for (int k = 0; k < 32; k++) {
        float r = s[k];
        r += __shfl_xor_sync(0xffffffffu, r, 8);
        r += __shfl_xor_sync(0xffffffffu, r, 4);
        r += __shfl_xor_sync(0xffffffffu, r, 2);
        r += __shfl_xor_sync(0xffffffffu, r, 1);
        if (l == 0)  pooled[2 * k]     = r * (1.f / 64.f);
        if (l == 16) pooled[2 * k + 1] = r * (1.f / 64.f);
    }
    __syncwarp();

    // gate: lanes 0..15 = experts; Wg column reads are lane-consecutive (L1-resident)
    float lgt = -3.0e38f;
    if (l < NEXP) {
        float d = bg[l];
#pragma unroll
        for (int j = 0; j < CDIM; j++) d += pooled[j] * Wg[j * NEXP + l];
        float v = d * (1.f / 1.5f);
        lgt = fminf(10.f, fmaxf(-10.f, v));
        out_logits[(size_t)n * NEXP + l] = lgt;
    }

    // softmax/argmax over lanes 0..15 (lanes 16..31 carry -inf, isolated groups)
    float m = lgt;
    int   mi = l & 15;
#pragma unroll
    for (int o = 8; o; o >>= 1) {
        float om = __shfl_xor_sync(0xffffffffu, m, o);
        int   oi = __shfl_xor_sync(0xffffffffu, mi, o);
        if (om > m || (om == m && oi < mi)) { m = om; mi = oi; }
    }
    float ev = (l < NEXP) ? expf(lgt - m) : 0.f;
    float sum = ev;
#pragma unroll
    for (int o = 8; o; o >>= 1) sum += __shfl_xor_sync(0xffffffffu, sum, o);
    if (l < NEXP) g_probs[n * NEXP + l] = ev / sum;

    if (l == 0) {
        float lse = m + logf(sum);
        g_lse2[n] = lse * lse;
        float pe = 1.f / sum;  // top-1 prob = exp(0)/sum
        g_expert[n] = mi;
        // key: expert (4b) | prob bits (monotonic, positive floats) | 8191-n (stable tie-break)
        unsigned long long key = ((unsigned long long)mi << 45)
                               | ((unsigned long long)__float_as_uint(pe) << 13)
                               | (unsigned long long)(8191 - n);
        g_keys[n] = key;
        int slot = atomicAdd(&g_bcnt[mi], 1);
        g_bkeys[mi * NTOK + slot] = key;
    }
}

// ---------------- kernel 2: fused rank + write-out ----------------
__global__ void __launch_bounds__(256) writeout_kernel(float* __restrict__ out) {
    __shared__ int s_warp[8];
    __shared__ int s_pos;
    const int n = blockIdx.x;
    const int t = threadIdx.x;

    // inline rank: count strictly-greater keys in this expert's bucket
    const unsigned long long mykey = g_keys[n];
    const int e = g_expert[n];
    const int m = g_bcnt[e];
    const unsigned long long* bk = g_bkeys + (size_t)e * NTOK;
    int cnt = 0;
    for (int j = t; j < m; j += 256) cnt += (int)(bk[j] > mykey);
#pragma unroll
    for (int o = 16; o; o >>= 1) cnt += __shfl_xor_sync(0xffffffffu, cnt, o);
    if ((t & 31) == 0) s_warp[t >> 5] = cnt;
    __syncthreads();
    if (t == 0) {
        int p = 0;
#pragma unroll
        for (int w = 0; w < 8; w++) p += s_warp[w];
        s_pos = p;
    }
    __syncthreads();
    const int pos = s_pos;

    const int hot = (pos < CAP) ? (e * CAP + pos) : -1;
    const int hot_v = hot >> 2;
    const int hot_e = hot & 3;

    float4* dsp = (float4*)(out + (size_t)n * (NEXP * CAP));
    float4* cmb = (float4*)(out + NEC + (size_t)n * (NEXP * CAP));

    const float4 z = make_float4(0.f, 0.f, 0.f, 0.f);
#pragma unroll
    for (int i = 0; i < 10; i++) {
        int idx = t + i * 256;
        float4 v = z;
        if (hot >= 0 && idx == hot_v) ((float*)&v)[hot_e] = 1.f;
        __stcs(&dsp[idx], v);
        __stcs(&cmb[idx], v);   // combine == dispatch for top-1 routing
    }
}

// ---------------- kernel 3: scalar losses (latency-bound; overlapped) -------
__global__ void finalize_kernel(const float* __restrict__ logits,
                                float* __restrict__ scal) {
    __shared__ float part[1024];
    __shared__ float cs[NEXP];
    __shared__ float res_z, res_s1, res_s2;
    int t = threadIdx.x;

    float cp = 0.f;
    for (int i = t; i < NTOK * NEXP; i += 1024) cp += g_probs[i];
    part[t] = cp;
    __syncthreads();
    if (t < NEXP) {
        float s = 0.f;
        for (int k = t; k < 1024; k += NEXP) s += part[k];
        cs[t] = s;
    }
    __syncthreads();

    float sz = 0.f;
    for (int i = t; i < NTOK; i += 1024) sz += g_lse2[i];
    part[t] = sz;
    __syncthreads();
    for (int o = 512; o; o >>= 1) { if (t < o) part[t] += part[t + o]; __syncthreads(); }
    if (t == 0) res_z = part[0];
    __syncthreads();

    float s1 = 0.f, s2 = 0.f;
    for (int i = t; i < NTOK * NEXP; i += 1024) {
        float v = logits[i];
        s1 += v; s2 += v * v;
    }
    part[t] = s1;
    __syncthreads();
    for (int o = 512; o; o >>= 1) { if (t < o) part[t] += part[t + o]; __syncthreads(); }
    if (t == 0) res_s1 = part[0];
    __syncthreads();
    part[t] = s2;
    __syncthreads();
    for (int o = 512; o; o >>= 1) { if (t < o) part[t] += part[t + o]; __syncthreads(); }
    if (t == 0) res_s2 = part[0];
    __syncthreads();

    if (t == 0) {
        scal[0] = res_z / (float)NTOK;  // z_loss
        float aux = 0.f;
        for (int e = 0; e < NEXP; e++) {
            int surv = g_bcnt[e] < CAP ? g_bcnt[e] : CAP;  // surviving tokens
            aux += ((float)surv / (float)NTOK) * (cs[e] / (float)NTOK);
        }
        scal[1] = aux * (float)NEXP;    // aux_loss
        float inv = 1.f / (float)(NTOK * NEXP);
        float mean = res_s1 * inv;
        float var = res_s2 * inv - mean * mean;
        scal[2] = sqrtf(fmaxf(var, 0.f));  // logits_std
    }
}

// ---------------- launch ----------------
extern "C" void kernel_launch(void* const* d_in, const int* in_sizes, int n_in,
                              void* d_out, int out_size) {
    const float* X  = (const float*)d_in[0];
    const float* Wg = (const float*)d_in[1];
    const float* bg = (const float*)d_in[2];
    float* out = (float*)d_out;

    static cudaStream_t s_side = nullptr;
    static cudaEvent_t  ev_gate = nullptr, ev_fin = nullptr;
    if (s_side == nullptr) {
        cudaStreamCreateWithFlags(&s_side, cudaStreamNonBlocking);
        cudaEventCreateWithFlags(&ev_gate, cudaEventDisableTiming);
        cudaEventCreateWithFlags(&ev_fin,  cudaEventDisableTiming);
    }

    // Phase 1 (pure read): gating fills keys/buckets/probs/lse2/logits
    init_kernel<<<1, 32>>>();
    gating_kernel<<<NTOK / 8, 256>>>(X, Wg, bg, out + LOGITS_OFF);
    cudaEventRecord(ev_gate, 0);

    // Latency-bound scalar losses fork after gating (hidden under write phase)
    cudaStreamWaitEvent(s_side, ev_gate, 0);
    finalize_kernel<<<1, 1024, 0, s_side>>>(out + LOGITS_OFF, out + SCALAR_OFF);
    cudaEventRecord(ev_fin, s_side);

    // Phase 2 (pure write): fused rank + zero-fill + one-hot, 672MB
    writeout_kernel<<<NTOK, 256>>>(out);

    cudaStreamWaitEvent(0, ev_fin, 0);
}

// round 8
// speedup vs baseline: 1.0654x; 1.0654x over previous
#include <cuda_runtime.h>
#include <cstdint>
#include <math.h>

#define NTOK 8192
#define CDIM 64
#define NEXP 16
#define CAP  640
#define NEC  ((size_t)NTOK * NEXP * CAP)       /* 83,886,080 elements */
#define SCALAR_OFF (2 * NEC)                   /* z, aux, std */
#define LOGITS_OFF (2 * NEC + 3)

// ---------------- scratch (no allocs allowed) ----------------
__device__ float              g_probs[NTOK * NEXP];
__device__ float              g_lse2[NTOK];
__device__ unsigned long long g_keys[NTOK];
__device__ int                g_expert[NTOK];
__device__ int                g_bcnt[NEXP];
__device__ unsigned long long g_bkeys[NEXP * NTOK];   // per-expert key buckets (1MB)

// ---------------- kernel 0: zero bucket counters ----------------
__global__ void init_kernel() {
    if (threadIdx.x < NEXP) g_bcnt[threadIdx.x] = 0;
}

// ---------------- kernel 1: pool + gate + softmax + bucket scatter ----------
// one block (64 threads) per token; coalesced streaming reads + smem transpose
__global__ void gating_kernel(const float* __restrict__ X,
                              const float* __restrict__ Wg,
                              const float* __restrict__ bg,
                              float* __restrict__ out_logits) {
    __shared__ float part[64 * 17];   // [channel][lane-in-channel], padded
    __shared__ float pooled[CDIM];
    __shared__ float lg[NEXP];
    const int n = blockIdx.x;
    const int c = threadIdx.x;  // 0..63

    // Coalesced: warp reads 512B contiguous per LDG round; evict-first (read-once)
    const float4* xp = (const float4*)(X + (size_t)n * (CDIM * 64));
#pragma unroll
    for (int i = 0; i < 16; i++) {
        float4 v = __ldcs(&xp[i * 64 + c]);
        part[(i * 4 + (c >> 4)) * 17 + (c & 15)] = (v.x + v.y) + (v.z + v.w);
    }
    __syncthreads();

    float s = 0.f;
#pragma unroll
    for (int j = 0; j < 16; j++) s += part[c * 17 + j];
    pooled[c] = s * (1.f / 64.f);
    __syncthreads();

    if (c < NEXP) {
        float d = bg[c];
#pragma unroll
        for (int k = 0; k < CDIM; k++) d += pooled[k] * Wg[k * NEXP + c];
        float l = d * (1.f / 1.5f);
        l = fminf(10.f, fmaxf(-10.f, l));
        lg[c] = l;
        out_logits[(size_t)n * NEXP + c] = l;
    }
    __syncthreads();

    if (c < 32) {  // warp 0: softmax/argmax; lanes 0..15 carry data
        float v = (c < 16) ? lg[c] : -3.0e38f;
        float m = v;
        int   mi = c;
#pragma unroll
        for (int o = 8; o; o >>= 1) {
            float om = __shfl_xor_sync(0xffffffffu, m, o);
            int   oi = __shfl_xor_sync(0xffffffffu, mi, o);
            if (om > m || (om == m && oi < mi)) { m = om; mi = oi; }
        }
        float ev = (c < 16) ? expf(v - m) : 0.f;
        float sum = ev;
#pragma unroll
        for (int o = 8; o; o >>= 1) sum += __shfl_xor_sync(0xffffffffu, sum, o);
        if (c < 16) g_probs[n * NEXP + c] = ev / sum;
        if (c == 0) {
            float lse = m + logf(sum);
            g_lse2[n] = lse * lse;
            float pe = 1.f / sum;  // top-1 prob = exp(0)/sum
            g_expert[n] = mi;
            // key: expert (4b) | prob bits (monotonic, positive floats) | 8191-n (stable tie-break)
            unsigned long long key = ((unsigned long long)mi << 45)
                                   | ((unsigned long long)__float_as_uint(pe) << 13)
                                   | (unsigned long long)(8191 - n);
            g_keys[n] = key;
            // bucket scatter (order in bucket irrelevant: rank recomputed by compares)
            int slot = atomicAdd(&g_bcnt[mi], 1);
            g_bkeys[mi * NTOK + slot] = key;
        }
    }
}

// ---------------- kernel 2: fused rank + write-out ----------------
// One block per token: scan own expert's bucket (L2-resident) for rank,
// then emit the token's dispatch & combine slabs (zeros + one hot element).
__global__ void __launch_bounds__(256) writeout_kernel(float* __restrict__ out) {
    __shared__ int s_warp[8];
    __shared__ int s_pos;
    const int n = blockIdx.x;
    const int t = threadIdx.x;

    // inline rank: count strictly-greater keys in this expert's bucket
    const unsigned long long mykey = g_keys[n];
    const int e = g_expert[n];
    const int m = g_bcnt[e];
    const unsigned long long* bk = g_bkeys + (size_t)e * NTOK;
    int cnt = 0;
    for (int j = t; j < m; j += 256) cnt += (int)(__ldcs(&bk[j]) > mykey);
#pragma unroll
    for (int o = 16; o; o >>= 1) cnt += __shfl_xor_sync(0xffffffffu, cnt, o);
    if ((t & 31) == 0) s_warp[t >> 5] = cnt;
    __syncthreads();
    if (t == 0) {
        int p = 0;
#pragma unroll
        for (int w = 0; w < 8; w++) p += s_warp[w];
        s_pos = p;
    }
    __syncthreads();
    const int pos = s_pos;

    const int hot = (pos < CAP) ? (e * CAP + pos) : -1;
    const int hot_v = hot >> 2;
    const int hot_e = hot & 3;

    float4* dsp = (float4*)(out + (size_t)n * (NEXP * CAP));
    float4* cmb = (float4*)(out + NEC + (size_t)n * (NEXP * CAP));

    const float4 z = make_float4(0.f, 0.f, 0.f, 0.f);
#pragma unroll
    for (int i = 0; i < 10; i++) {
        int idx = t + i * 256;
        float4 v = z;
        if (hot >= 0 && idx == hot_v) ((float*)&v)[hot_e] = 1.f;
        __stcs(&dsp[idx], v);   // streaming (evict-first) stores
        __stcs(&cmb[idx], v);   // combine == dispatch for top-1 routing
    }
}

// ---------------- kernel 3: scalar losses (latency-bound; overlapped) -------
// Depends only on gating outputs: surviving count per expert = min(bcnt, CAP).
__global__ void finalize_kernel(const float* __restrict__ logits,
                                float* __restrict__ scal) {
    __shared__ float part[1024];
    __shared__ float cs[NEXP];
    __shared__ float res_z, res_s1, res_s2;
    int t = threadIdx.x;

    // per-expert prob column sums: thread t only touches column t&15
    float cp = 0.f;
    for (int i = t; i < NTOK * NEXP; i += 1024) cp += g_probs[i];
    part[t] = cp;
    __syncthreads();
    if (t < NEXP) {
        float s = 0.f;
        for (int k = t; k < 1024; k += NEXP) s += part[k];
        cs[t] = s;
    }
    __syncthreads();

    float sz = 0.f;
    for (int i = t; i < NTOK; i += 1024) sz += g_lse2[i];
    part[t] = sz;
    __syncthreads();
    for (int o = 512; o; o >>= 1) { if (t < o) part[t] += part[t + o]; __syncthreads(); }
    if (t == 0) res_z = part[0];
    __syncthreads();

    float s1 = 0.f, s2 = 0.f;
    for (int i = t; i < NTOK * NEXP; i += 1024) {
        float v = logits[i];
        s1 += v; s2 += v * v;
    }
    part[t] = s1;
    __syncthreads();
    for (int o = 512; o; o >>= 1) { if (t < o) part[t] += part[t + o]; __syncthreads(); }
    if (t == 0) res_s1 = part[0];
    __syncthreads();
    part[t] = s2;
    __syncthreads();
    for (int o = 512; o; o >>= 1) { if (t < o) part[t] += part[t + o]; __syncthreads(); }
    if (t == 0) res_s2 = part[0];
    __syncthreads();

    if (t == 0) {
        scal[0] = res_z / (float)NTOK;  // z_loss
        float aux = 0.f;
        for (int e = 0; e < NEXP; e++) {
            int surv = g_bcnt[e] < CAP ? g_bcnt[e] : CAP;  // surviving tokens
            aux += ((float)surv / (float)NTOK) * (cs[e] / (float)NTOK);
        }
        scal[1] = aux * (float)NEXP;    // aux_loss
        float inv = 1.f / (float)(NTOK * NEXP);
        float mean = res_s1 * inv;
        float var = res_s2 * inv - mean * mean;
        scal[2] = sqrtf(fmaxf(var, 0.f));  // logits_std
    }
}

// ---------------- launch ----------------
extern "C" void kernel_launch(void* const* d_in, const int* in_sizes, int n_in,
                              void* d_out, int out_size) {
    const float* X  = (const float*)d_in[0];
    const float* Wg = (const float*)d_in[1];
    const float* bg = (const float*)d_in[2];
    float* out = (float*)d_out;

    static cudaStream_t s_side = nullptr;
    static cudaEvent_t  ev_gate = nullptr, ev_fin = nullptr;
    if (s_side == nullptr) {
        cudaStreamCreateWithFlags(&s_side, cudaStreamNonBlocking);
        cudaEventCreateWithFlags(&ev_gate, cudaEventDisableTiming);
        cudaEventCreateWithFlags(&ev_fin,  cudaEventDisableTiming);
    }

    // Phase 1 (pure read): gating fills keys/buckets/probs/lse2/logits
    init_kernel<<<1, 32>>>();
    gating_kernel<<<NTOK, 64>>>(X, Wg, bg, out + LOGITS_OFF);
    cudaEventRecord(ev_gate, 0);

    // Latency-bound scalar losses fork after gating (hidden under write phase)
    cudaStreamWaitEvent(s_side, ev_gate, 0);
    finalize_kernel<<<1, 1024, 0, s_side>>>(out + LOGITS_OFF, out + SCALAR_OFF);
    cudaEventRecord(ev_fin, s_side);

    // Phase 2 (pure write): fused rank + zero-fill + one-hot, 672MB
    writeout_kernel<<<NTOK, 256>>>(out);

    cudaStreamWaitEvent(0, ev_fin, 0);
}